// round 4
// baseline (speedup 1.0000x reference)
#include <cuda_runtime.h>

#define BATCH 128
#define SEQ   2048
#define FEAT  64
#define UNITS 64
#define GATES 256   // 4*UNITS
#define OUTD  6

// Precomputed x@W0 + b0, PERMUTED column layout, [B][T][256] (+pad for prefetch over-read)
__device__ float g_pre0[(size_t)BATCH * SEQ * GATES + GATES];

typedef unsigned long long u64;

// ---- packed f32x2 helpers -------------------------------------------------
__device__ __forceinline__ u64 pk(float lo, float hi) {
    u64 r; asm("mov.b64 %0, {%1, %2};" : "=l"(r) : "f"(lo), "f"(hi)); return r;
}
__device__ __forceinline__ void upk(u64 v, float& lo, float& hi) {
    asm("mov.b64 {%0, %1}, %2;" : "=f"(lo), "=f"(hi) : "l"(v));
}
__device__ __forceinline__ void fma2(u64& d, u64 a, u64 b) {
    asm("fma.rn.f32x2 %0, %1, %2, %0;" : "+l"(d) : "l"(a), "l"(b));
}
__device__ __forceinline__ float red4(u64 a, u64 b) {
    float x0, x1, x2, x3; upk(a, x0, x1); upk(b, x2, x3);
    return (x0 + x1) + (x2 + x3);
}

// ---- fast, accurate activations (MUFU EX2/RCP, ~1e-7 rel err) -------------
__device__ __forceinline__ float sig_fast(float x) {
    return __fdividef(1.f, 1.f + __expf(-x));
}
__device__ __forceinline__ float tanh_fast(float x) {
    float e = __expf(fminf(-2.f * x, 30.f));
    return __fdividef(1.f - e, 1.f + e);
}
// Unified gate activation: tanh for candidate gate, sigmoid otherwise.
// act(z) = (1 - s*e) / (1 + e) with e = exp(m*z):  sigmoid: m=-1,s=0 ; tanh: m=-2,s=1
__device__ __forceinline__ float gate_act(float z, float m, float s) {
    float e = __expf(fminf(m * z, 30.f));
    return __fdividef(1.f - s * e, 1.f + e);
}

// Column permutation: column q <-> gate column (q&3)*64 + (q>>2)
__device__ __forceinline__ int PERM(int q) { return ((q & 3) << 6) + (q >> 2); }

// ===========================================================================
// Kernel 1: pre0[b][t][j] = (x[b][t] @ W0 + b0)[PERM(j)], 2-timestep unroll
// ===========================================================================
__global__ void __launch_bounds__(256) precompute_kernel(
    const float* __restrict__ x, const float* __restrict__ W0,
    const float* __restrict__ b0)
{
    __shared__ __align__(16) float xs[128 * FEAT];   // 32 KB
    const int b   = blockIdx.x;
    const int t0  = blockIdx.y * 128;
    const int j   = threadIdx.x;
    const int col = PERM(j);

    u64 w[32];
#pragma unroll
    for (int m = 0; m < 32; m++)
        w[m] = pk(W0[(2 * m) * GATES + col], W0[(2 * m + 1) * GATES + col]);
    const float bias = b0[col];

    const float4* xp = (const float4*)(x + ((size_t)b * SEQ + t0) * FEAT);
    float4* xsv = (float4*)xs;
    for (int i = j; i < 128 * FEAT / 4; i += 256) xsv[i] = xp[i];
    __syncthreads();

    float* outp = g_pre0 + ((size_t)b * SEQ + t0) * GATES;
    for (int t = 0; t < 128; t += 2) {
        u64 a0 = pk(bias, 0.f), a1 = 0ull;
        u64 b0a = pk(bias, 0.f), b1a = 0ull;
        const float4* hx0 = (const float4*)(xs + t * FEAT);
        const float4* hx1 = (const float4*)(xs + (t + 1) * FEAT);
#pragma unroll
        for (int m = 0; m < 16; m++) {
            float4 q0 = hx0[m];
            fma2(a0,  pk(q0.x, q0.y), w[2 * m]);
            fma2(a1,  pk(q0.z, q0.w), w[2 * m + 1]);
            float4 q1 = hx1[m];
            fma2(b0a, pk(q1.x, q1.y), w[2 * m]);
            fma2(b1a, pk(q1.z, q1.w), w[2 * m + 1]);
        }
        outp[(size_t)t * GATES + j]       = red4(a0, a1);
        outp[(size_t)(t + 1) * GATES + j] = red4(b0a, b1a);
    }
}

// ===========================================================================
// Kernel 2: persistent recurrence. 128 blocks x 512 threads (k-split x2).
// Thread j = (u<<3)|(g<<1)|kh : column q=j>>1 (gate g=q&3, unit u=q>>2),
// k-half kh=j&1. Per phase: 8x(LDS.128 + 2 fma2) per GEMV-half, then
// shfl_xor(1) k-combine, activation, shfl_xor(2/4/6) gate gather, c/h update.
// 3 barriers/step.
// ===========================================================================
__global__ void __launch_bounds__(512) rnn_kernel(
    const float* __restrict__ U0g, const float* __restrict__ W1g,
    const float* __restrict__ U1g, const float* __restrict__ b1g,
    const float* __restrict__ Wf,  const float* __restrict__ bfv,
    const float* __restrict__ Wo,  const float* __restrict__ bo,
    float* __restrict__ out)
{
    __shared__ __align__(16) float h0buf[2][UNITS];
    __shared__ __align__(16) float h1s[UNITS];
    __shared__ __align__(16) float h2s[UNITS];
    __shared__ __align__(16) float fs[64];

    const int j   = threadIdx.x;          // 0..511
    const int b   = blockIdx.x;
    const int q   = j >> 1;               // column 0..255
    const int kh  = j & 1;                // k-half
    const int col = PERM(q);
    const int u   = q >> 2;               // unit
    const bool wr  = ((j & 7) == 0);      // writer lane (g==0, kh==0)
    const bool isg = ((q & 3) == 2);
    const float am = isg ? -2.f : -1.f;   // activation params (hoisted)
    const float as = isg ?  1.f :  0.f;

    // Weight half-columns in registers: k = kh*32 + [0,32)
    u64 u0[16], w1[16], u1[16];
    const int kb = kh * 32;
#pragma unroll
    for (int m = 0; m < 16; m++) {
        const int k0 = kb + 2 * m;
        u0[m] = pk(U0g[k0 * GATES + col], U0g[(k0 + 1) * GATES + col]);
        w1[m] = pk(W1g[k0 * GATES + col], W1g[(k0 + 1) * GATES + col]);
        u1[m] = pk(U1g[k0 * GATES + col], U1g[(k0 + 1) * GATES + col]);
    }
    const float bias1 = kh ? 0.f : b1g[col];

    float c0 = 0.f, c1 = 0.f, c2 = 0.f;   // valid on g==0 lanes
    if (j < UNITS) { h0buf[0][j] = 0.f; h1s[j] = 0.f; h2s[j] = 0.f; }
    __syncthreads();

    const float* prep = g_pre0 + (size_t)b * SEQ * GATES + q;
    float pre = *prep;
    const int f4off = kh * 8;             // float4 offset of this thread's k-half

    for (int t = 0; t < SEQ; t++) {
        const float4* H0r = (const float4*)h0buf[t & 1] + f4off;
        float*        h0w = h0buf[(t & 1) ^ 1];
        const float4* H1  = (const float4*)h1s + f4off;
        const float4* H2  = (const float4*)h2s + f4off;

        // ---------------- Phase A ----------------
        u64 z0a = pk(kh ? 0.f : pre, 0.f), z0b = 0ull;
        u64 p1a = pk(bias1, 0.f),          p1b = 0ull;
        u64 p2a = pk(bias1, 0.f),          p2b = 0ull;
        prep += GATES;
        pre = *prep;                      // prefetch next step (padded tail)
#pragma unroll
        for (int m = 0; m < 8; m++) {
            float4 q0 = H0r[m];
            fma2(z0a, pk(q0.x, q0.y), u0[2 * m]);
            fma2(z0b, pk(q0.z, q0.w), u0[2 * m + 1]);
            float4 q1 = H1[m];
            fma2(p1a, pk(q1.x, q1.y), u1[2 * m]);
            fma2(p1b, pk(q1.z, q1.w), u1[2 * m + 1]);
            float4 q2 = H2[m];
            fma2(p2a, pk(q2.x, q2.y), u1[2 * m]);
            fma2(p2b, pk(q2.z, q2.w), u1[2 * m + 1]);
        }
        {
            float zp = red4(z0a, z0b);
            zp += __shfl_xor_sync(0xffffffffu, zp, 1);      // k-combine
            float a  = gate_act(zp, am, as);
            float v1 = __shfl_xor_sync(0xffffffffu, a, 2);  // gate g^1
            float v2 = __shfl_xor_sync(0xffffffffu, a, 4);  // gate g^2
            float v3 = __shfl_xor_sync(0xffffffffu, a, 6);  // gate g^3
            c0 = v1 * c0 + a * v2;                          // valid on g==0 lanes
            float h = v3 * tanh_fast(c0);
            if (wr) h0w[u] = h;
        }
        __syncthreads();

        // ---------------- Phase B: z1 = p1 + h0_new @ W1 ----------------
        {
            const float4* H0n = (const float4*)h0w + f4off;
#pragma unroll
            for (int m = 0; m < 8; m++) {
                float4 qq = H0n[m];
                fma2(p1a, pk(qq.x, qq.y), w1[2 * m]);
                fma2(p1b, pk(qq.z, qq.w), w1[2 * m + 1]);
            }
            float zp = red4(p1a, p1b);
            zp += __shfl_xor_sync(0xffffffffu, zp, 1);
            float a  = gate_act(zp, am, as);
            float v1 = __shfl_xor_sync(0xffffffffu, a, 2);
            float v2 = __shfl_xor_sync(0xffffffffu, a, 4);
            float v3 = __shfl_xor_sync(0xffffffffu, a, 6);
            c1 = v1 * c1 + a * v2;
            float h = v3 * tanh_fast(c1);
            if (wr) h1s[u] = h;
        }
        __syncthreads();

        // ---------------- Phase C: z2 = p2 + h1_new @ W1 ----------------
        {
#pragma unroll
            for (int m = 0; m < 8; m++) {
                float4 qq = H1[m];                 // h1s, updated in phase B
                fma2(p2a, pk(qq.x, qq.y), w1[2 * m]);
                fma2(p2b, pk(qq.z, qq.w), w1[2 * m + 1]);
            }
            float zp = red4(p2a, p2b);
            zp += __shfl_xor_sync(0xffffffffu, zp, 1);
            float a  = gate_act(zp, am, as);
            float v1 = __shfl_xor_sync(0xffffffffu, a, 2);
            float v2 = __shfl_xor_sync(0xffffffffu, a, 4);
            float v3 = __shfl_xor_sync(0xffffffffu, a, 6);
            c2 = v1 * c2 + a * v2;
            float h = v3 * tanh_fast(c2);
            if (wr) h2s[u] = h;
        }
        __syncthreads();
    }

    // ---------------- Epilogue: y = relu(h2 @ Wf + bf) @ Wo + bo ------------
    if (j < 64) {
        float acc = bfv[j];
#pragma unroll
        for (int k = 0; k < 64; k++) acc = fmaf(h2s[k], Wf[k * 64 + j], acc);
        fs[j] = fmaxf(acc, 0.f);
    }
    __syncthreads();
    if (j < OUTD) {
        float acc = bo[j];
#pragma unroll
        for (int k = 0; k < 64; k++) acc = fmaf(fs[k], Wo[k * OUTD + j], acc);
        out[b * OUTD + j] = acc;
    }
}

// ===========================================================================
extern "C" void kernel_launch(void* const* d_in, const int* in_sizes, int n_in,
                              void* d_out, int out_size)
{
    const float* x  = (const float*)d_in[0];
    const float* W0 = (const float*)d_in[1];
    const float* U0 = (const float*)d_in[2];
    const float* b0 = (const float*)d_in[3];
    const float* W1 = (const float*)d_in[4];
    const float* U1 = (const float*)d_in[5];
    const float* b1 = (const float*)d_in[6];
    const float* Wf = (const float*)d_in[7];
    const float* bf = (const float*)d_in[8];
    const float* Wo = (const float*)d_in[9];
    const float* bo = (const float*)d_in[10];

    dim3 pg(BATCH, SEQ / 128);
    precompute_kernel<<<pg, 256>>>(x, W0, b0);
    rnn_kernel<<<BATCH, 512>>>(U0, W1, U1, b1, Wf, bf, Wo, bo, (float*)d_out);
}

// round 5
// speedup vs baseline: 1.8511x; 1.8511x over previous
#include <cuda_runtime.h>

#define BATCH 128
#define SEQ   2048
#define FEAT  64
#define UNITS 64
#define GATES 256   // 4*UNITS
#define OUTD  6

// Precomputed x@W0 + b0, PERMUTED column layout, [B][T][256] (+pad: pipeline prefetch overshoots)
__device__ float g_pre0[(size_t)BATCH * SEQ * GATES + 4 * GATES];

typedef unsigned long long u64;

// ---- packed f32x2 helpers -------------------------------------------------
__device__ __forceinline__ u64 pk(float lo, float hi) {
    u64 r; asm("mov.b64 %0, {%1, %2};" : "=l"(r) : "f"(lo), "f"(hi)); return r;
}
__device__ __forceinline__ void upk(u64 v, float& lo, float& hi) {
    asm("mov.b64 {%0, %1}, %2;" : "=f"(lo), "=f"(hi) : "l"(v));
}
__device__ __forceinline__ void fma2(u64& d, u64 a, u64 b) {
    asm("fma.rn.f32x2 %0, %1, %2, %0;" : "+l"(d) : "l"(a), "l"(b));
}
__device__ __forceinline__ float red4(u64 a, u64 b) {
    float x0, x1, x2, x3; upk(a, x0, x1); upk(b, x2, x3);
    return (x0 + x1) + (x2 + x3);
}

// ---- fast activations (MUFU EX2/RCP, ~1e-7 rel err) -----------------------
__device__ __forceinline__ float tanh_fast(float x) {
    float e = __expf(fminf(-2.f * x, 30.f));
    return __fdividef(1.f - e, 1.f + e);
}
// act(z) = (1 - s*e)/(1 + e), e = exp(m*z):  sigmoid m=-1,s=0 ; tanh m=-2,s=1
__device__ __forceinline__ float gate_act(float z, float m, float s) {
    float e = __expf(fminf(m * z, 30.f));
    return __fdividef(1.f - s * e, 1.f + e);
}

// Column permutation: column q <-> gate column (q&3)*64 + (q>>2)
__device__ __forceinline__ int PERM(int q) { return ((q & 3) << 6) + (q >> 2); }

// ===========================================================================
// Kernel 1: pre0[b][t][j] = (x[b][t] @ W0 + b0)[PERM(j)], 2-timestep unroll
// ===========================================================================
__global__ void __launch_bounds__(256) precompute_kernel(
    const float* __restrict__ x, const float* __restrict__ W0,
    const float* __restrict__ b0)
{
    __shared__ __align__(16) float xs[128 * FEAT];   // 32 KB
    const int b   = blockIdx.x;
    const int t0  = blockIdx.y * 128;
    const int j   = threadIdx.x;
    const int col = PERM(j);

    u64 w[32];
#pragma unroll
    for (int m = 0; m < 32; m++)
        w[m] = pk(W0[(2 * m) * GATES + col], W0[(2 * m + 1) * GATES + col]);
    const float bias = b0[col];

    const float4* xp = (const float4*)(x + ((size_t)b * SEQ + t0) * FEAT);
    float4* xsv = (float4*)xs;
    for (int i = j; i < 128 * FEAT / 4; i += 256) xsv[i] = xp[i];
    __syncthreads();

    float* outp = g_pre0 + ((size_t)b * SEQ + t0) * GATES;
    for (int t = 0; t < 128; t += 2) {
        u64 a0 = pk(bias, 0.f), a1 = 0ull;
        u64 b0a = pk(bias, 0.f), b1a = 0ull;
        const float4* hx0 = (const float4*)(xs + t * FEAT);
        const float4* hx1 = (const float4*)(xs + (t + 1) * FEAT);
#pragma unroll
        for (int m = 0; m < 16; m++) {
            float4 q0 = hx0[m];
            fma2(a0,  pk(q0.x, q0.y), w[2 * m]);
            fma2(a1,  pk(q0.z, q0.w), w[2 * m + 1]);
            float4 q1 = hx1[m];
            fma2(b0a, pk(q1.x, q1.y), w[2 * m]);
            fma2(b1a, pk(q1.z, q1.w), w[2 * m + 1]);
        }
        outp[(size_t)t * GATES + j]       = red4(a0, a1);
        outp[(size_t)(t + 1) * GATES + j] = red4(b0a, b1a);
    }
}

// ===========================================================================
// Kernel 2: persistent recurrence, CELLS PIPELINED ACROSS TIME.
// 128 blocks x 256 threads. Thread j: gate g=j&3 of unit u=j>>2 (col PERM(j)).
// Tick tau computes: cell0 @ t=tau, cell1 @ t=tau-1, cell2 @ t=tau-2.
// All inputs of a tick were produced in the previous tick -> ONE barrier/tick.
// h arrays ping-pong by tick parity. h0 load shared by cell0&1; h1 by cell1&2.
// ===========================================================================
__global__ void __launch_bounds__(256) rnn_kernel(
    const float* __restrict__ U0g, const float* __restrict__ W1g,
    const float* __restrict__ U1g, const float* __restrict__ b1g,
    const float* __restrict__ Wf,  const float* __restrict__ bfv,
    const float* __restrict__ Wo,  const float* __restrict__ bo,
    float* __restrict__ out)
{
    __shared__ __align__(16) float h0buf[2][UNITS];
    __shared__ __align__(16) float h1buf[2][UNITS];
    __shared__ __align__(16) float h2buf[2][UNITS];
    __shared__ __align__(16) float fs[64];

    const int j   = threadIdx.x;          // 0..255
    const int b   = blockIdx.x;
    const int col = PERM(j);
    const int u   = j >> 2;
    const bool wr  = ((j & 3) == 0);
    const bool isg = ((j & 3) == 2);
    const float am = isg ? -2.f : -1.f;
    const float as = isg ?  1.f :  0.f;

    // Weight columns in registers, k-packed (96 u64 = 192 regs).
    u64 u0[32], w1[32], u1[32];
#pragma unroll
    for (int m = 0; m < 32; m++) {
        u0[m] = pk(U0g[(2 * m) * GATES + col], U0g[(2 * m + 1) * GATES + col]);
        w1[m] = pk(W1g[(2 * m) * GATES + col], W1g[(2 * m + 1) * GATES + col]);
        u1[m] = pk(U1g[(2 * m) * GATES + col], U1g[(2 * m + 1) * GATES + col]);
    }
    const float bias1 = b1g[col];

    float c0 = 0.f, c1 = 0.f, c2 = 0.f;   // valid on g==0 lanes
    if (j < UNITS) {
        h0buf[0][j] = 0.f; h0buf[1][j] = 0.f;
        h1buf[0][j] = 0.f; h1buf[1][j] = 0.f;
        h2buf[0][j] = 0.f; h2buf[1][j] = 0.f;
    }
    __syncthreads();

    const float* prep = g_pre0 + (size_t)b * SEQ * GATES + j;
    float pre = *prep;                    // pre for tau=0

#pragma unroll 2
    for (int tau = 0; tau < SEQ + 2; tau++) {
        const int rp = tau & 1, wp = rp ^ 1;
        const float4* H0 = (const float4*)h0buf[rp];
        const float4* H1 = (const float4*)h1buf[rp];
        const float4* H2 = (const float4*)h2buf[rp];

        // Accumulators: z0 = pre + h0@U0 ; z1 = b1 + h0@W1 + h1@U1 ;
        //               z2 = b1 + h1@W1 + h2@U1
        u64 z0a = pk(pre, 0.f),   z0b = 0ull;
        u64 z1a = pk(bias1, 0.f), z1b = 0ull, z1c = 0ull, z1d = 0ull;
        u64 z2a = pk(bias1, 0.f), z2b = 0ull, z2c = 0ull, z2d = 0ull;

        prep += GATES;
        pre = *prep;                      // prefetch next tick (padded tail)

#pragma unroll
        for (int m = 0; m < 16; m++) {
            float4 q0 = H0[m];
            u64 a0 = pk(q0.x, q0.y), a1 = pk(q0.z, q0.w);
            fma2(z0a, a0, u0[2 * m]);  fma2(z0b, a1, u0[2 * m + 1]);
            fma2(z1a, a0, w1[2 * m]);  fma2(z1b, a1, w1[2 * m + 1]);
            float4 q1 = H1[m];
            u64 b0v = pk(q1.x, q1.y), b1v = pk(q1.z, q1.w);
            fma2(z1c, b0v, u1[2 * m]); fma2(z1d, b1v, u1[2 * m + 1]);
            fma2(z2a, b0v, w1[2 * m]); fma2(z2b, b1v, w1[2 * m + 1]);
            float4 q2 = H2[m];
            fma2(z2c, pk(q2.x, q2.y), u1[2 * m]);
            fma2(z2d, pk(q2.z, q2.w), u1[2 * m + 1]);
        }

        // ---- cell0 update (t = tau) ----
        if (tau < SEQ) {
            float z = red4(z0a, z0b);
            float a  = gate_act(z, am, as);
            float v1 = __shfl_xor_sync(0xffffffffu, a, 1);
            float v2 = __shfl_xor_sync(0xffffffffu, a, 2);
            float v3 = __shfl_xor_sync(0xffffffffu, a, 3);
            c0 = v1 * c0 + a * v2;
            float h = v3 * tanh_fast(c0);
            if (wr) h0buf[wp][u] = h;
        }
        // ---- cell1 update (t = tau-1) ----
        if ((unsigned)(tau - 1) < SEQ) {
            float z = red4(z1a, z1b) + red4(z1c, z1d);
            float a  = gate_act(z, am, as);
            float v1 = __shfl_xor_sync(0xffffffffu, a, 1);
            float v2 = __shfl_xor_sync(0xffffffffu, a, 2);
            float v3 = __shfl_xor_sync(0xffffffffu, a, 3);
            c1 = v1 * c1 + a * v2;
            float h = v3 * tanh_fast(c1);
            if (wr) h1buf[wp][u] = h;
        }
        // ---- cell2 update (t = tau-2) ----
        if ((unsigned)(tau - 2) < SEQ) {
            float z = red4(z2a, z2b) + red4(z2c, z2d);
            float a  = gate_act(z, am, as);
            float v1 = __shfl_xor_sync(0xffffffffu, a, 1);
            float v2 = __shfl_xor_sync(0xffffffffu, a, 2);
            float v3 = __shfl_xor_sync(0xffffffffu, a, 3);
            c2 = v1 * c2 + a * v2;
            float h = v3 * tanh_fast(c2);
            if (wr) h2buf[wp][u] = h;
        }
        __syncthreads();
    }

    // After tick SEQ+1, h2(SEQ-1) is in h2buf[SEQ & 1]  (written at tau=SEQ+1 to wp=(SEQ+1+1)&1 = SEQ&1).
    const float* h2f = h2buf[SEQ & 1];

    // ---------------- Epilogue: y = relu(h2 @ Wf + bf) @ Wo + bo ------------
    if (j < 64) {
        float acc = bfv[j];
#pragma unroll
        for (int k = 0; k < 64; k++) acc = fmaf(h2f[k], Wf[k * 64 + j], acc);
        fs[j] = fmaxf(acc, 0.f);
    }
    __syncthreads();
    if (j < OUTD) {
        float acc = bo[j];
#pragma unroll
        for (int k = 0; k < 64; k++) acc = fmaf(fs[k], Wo[k * OUTD + j], acc);
        out[b * OUTD + j] = acc;
    }
}

// ===========================================================================
extern "C" void kernel_launch(void* const* d_in, const int* in_sizes, int n_in,
                              void* d_out, int out_size)
{
    const float* x  = (const float*)d_in[0];
    const float* W0 = (const float*)d_in[1];
    const float* U0 = (const float*)d_in[2];
    const float* b0 = (const float*)d_in[3];
    const float* W1 = (const float*)d_in[4];
    const float* U1 = (const float*)d_in[5];
    const float* b1 = (const float*)d_in[6];
    const float* Wf = (const float*)d_in[7];
    const float* bf = (const float*)d_in[8];
    const float* Wo = (const float*)d_in[9];
    const float* bo = (const float*)d_in[10];

    dim3 pg(BATCH, SEQ / 128);
    precompute_kernel<<<pg, 256>>>(x, W0, b0);
    rnn_kernel<<<BATCH, 256>>>(U0, W1, U1, b1, Wf, bf, Wo, bo, (float*)d_out);
}

// round 6
// speedup vs baseline: 2.0074x; 1.0845x over previous
#include <cuda_runtime.h>

#define BATCH 128
#define SEQ   2048
#define FEAT  64
#define UNITS 64
#define GATES 256   // 4*UNITS
#define OUTD  6

// Precomputed x@W0 + b0, PERMUTED column layout, [B][T][256] (+pad: pipeline prefetch overshoots)
__device__ float g_pre0[(size_t)BATCH * SEQ * GATES + 4 * GATES];

typedef unsigned long long u64;

// ---- packed f32x2 helpers -------------------------------------------------
__device__ __forceinline__ u64 pk(float lo, float hi) {
    u64 r; asm("mov.b64 %0, {%1, %2};" : "=l"(r) : "f"(lo), "f"(hi)); return r;
}
__device__ __forceinline__ void upk(u64 v, float& lo, float& hi) {
    asm("mov.b64 {%0, %1}, %2;" : "=f"(lo), "=f"(hi) : "l"(v));
}
__device__ __forceinline__ void fma2(u64& d, u64 a, u64 b) {
    asm("fma.rn.f32x2 %0, %1, %2, %0;" : "+l"(d) : "l"(a), "l"(b));
}
__device__ __forceinline__ u64 addx2(u64 a, u64 b) {
    u64 r; asm("add.rn.f32x2 %0, %1, %2;" : "=l"(r) : "l"(a), "l"(b)); return r;
}
__device__ __forceinline__ float red4(u64 a, u64 b) {
    float x0, x1, x2, x3; upk(a, x0, x1); upk(b, x2, x3);
    return (x0 + x1) + (x2 + x3);
}

// ---- raw MUFU helpers (same numerics as __expf/__fdividef path) -----------
__device__ __forceinline__ float ex2_ap(float x) {
    float r; asm("ex2.approx.f32 %0, %1;" : "=f"(r) : "f"(x)); return r;
}
__device__ __forceinline__ float rcp_ap(float x) {
    float r; asm("rcp.approx.f32 %0, %1;" : "=f"(r) : "f"(x)); return r;
}
// act(z) = (1 - s*e) * rcp(1+e), e = 2^(min(m2*z, 40)):
//   sigmoid: m2=-log2e,  s=0 ; tanh: m2=-2log2e, s=1
__device__ __forceinline__ float gate_act(float z, float m2, float s) {
    float e = ex2_ap(fminf(m2 * z, 40.f));
    return (1.f - s * e) * rcp_ap(1.f + e);
}
__device__ __forceinline__ float tanh_fast(float x) {
    float e = ex2_ap(fminf(-2.885390082f * x, 40.f));
    return (1.f - e) * rcp_ap(1.f + e);
}

// Column permutation: column q <-> gate column (q&3)*64 + (q>>2)
__device__ __forceinline__ int PERM(int q) { return ((q & 3) << 6) + (q >> 2); }

// ===========================================================================
// Kernel 1: pre0[b][t][j] = (x[b][t] @ W0 + b0)[PERM(j)], 4-timestep unroll
// ===========================================================================
__global__ void __launch_bounds__(256) precompute_kernel(
    const float* __restrict__ x, const float* __restrict__ W0,
    const float* __restrict__ b0)
{
    __shared__ __align__(16) float xs[128 * FEAT];   // 32 KB
    const int b   = blockIdx.x;
    const int t0  = blockIdx.y * 128;
    const int j   = threadIdx.x;
    const int col = PERM(j);

    u64 w[32];
#pragma unroll
    for (int m = 0; m < 32; m++)
        w[m] = pk(W0[(2 * m) * GATES + col], W0[(2 * m + 1) * GATES + col]);
    const float bias = b0[col];

    const float4* xp = (const float4*)(x + ((size_t)b * SEQ + t0) * FEAT);
    float4* xsv = (float4*)xs;
    for (int i = j; i < 128 * FEAT / 4; i += 256) xsv[i] = xp[i];
    __syncthreads();

    float* outp = g_pre0 + ((size_t)b * SEQ + t0) * GATES;
    for (int t = 0; t < 128; t += 4) {
        u64 acc[8];
#pragma unroll
        for (int r = 0; r < 4; r++) { acc[2 * r] = pk(bias, 0.f); acc[2 * r + 1] = 0ull; }
        const float4* hx0 = (const float4*)(xs + (t + 0) * FEAT);
        const float4* hx1 = (const float4*)(xs + (t + 1) * FEAT);
        const float4* hx2 = (const float4*)(xs + (t + 2) * FEAT);
        const float4* hx3 = (const float4*)(xs + (t + 3) * FEAT);
#pragma unroll
        for (int m = 0; m < 16; m++) {
            float4 q0 = hx0[m];
            fma2(acc[0], pk(q0.x, q0.y), w[2 * m]);
            fma2(acc[1], pk(q0.z, q0.w), w[2 * m + 1]);
            float4 q1 = hx1[m];
            fma2(acc[2], pk(q1.x, q1.y), w[2 * m]);
            fma2(acc[3], pk(q1.z, q1.w), w[2 * m + 1]);
            float4 q2 = hx2[m];
            fma2(acc[4], pk(q2.x, q2.y), w[2 * m]);
            fma2(acc[5], pk(q2.z, q2.w), w[2 * m + 1]);
            float4 q3 = hx3[m];
            fma2(acc[6], pk(q3.x, q3.y), w[2 * m]);
            fma2(acc[7], pk(q3.z, q3.w), w[2 * m + 1]);
        }
#pragma unroll
        for (int r = 0; r < 4; r++)
            outp[(size_t)(t + r) * GATES + j] = red4(acc[2 * r], acc[2 * r + 1]);
    }
}

// ===========================================================================
// Kernel 2: persistent recurrence, CELLS PIPELINED ACROSS TIME.
// 128 blocks x 256 threads. Thread j: gate g=j&3 of unit u=j>>2 (col PERM(j)).
// Tick tau: cell0 @ t=tau, cell1 @ t=tau-1, cell2 @ t=tau-2. 1 barrier/tick.
// Warm-up/drain ticks are PEELED so the main loop is branch-free.
// ===========================================================================
__global__ void __launch_bounds__(256) rnn_kernel(
    const float* __restrict__ U0g, const float* __restrict__ W1g,
    const float* __restrict__ U1g, const float* __restrict__ b1g,
    const float* __restrict__ Wf,  const float* __restrict__ bfv,
    const float* __restrict__ Wo,  const float* __restrict__ bo,
    float* __restrict__ out)
{
    __shared__ __align__(16) float h0buf[2][UNITS];
    __shared__ __align__(16) float h1buf[2][UNITS];
    __shared__ __align__(16) float h2buf[2][UNITS];
    __shared__ __align__(16) float fs[64];

    const int j   = threadIdx.x;          // 0..255
    const int b   = blockIdx.x;
    const int col = PERM(j);
    const int u   = j >> 2;
    const bool wr  = ((j & 3) == 0);
    const bool isg = ((j & 3) == 2);
    const float am2 = isg ? -2.885390082f : -1.442695041f;  // -k*log2(e)
    const float as  = isg ?  1.f : 0.f;

    // Weight columns in registers, k-packed (96 u64 = 192 regs).
    u64 u0[32], w1[32], u1[32];
#pragma unroll
    for (int m = 0; m < 32; m++) {
        u0[m] = pk(U0g[(2 * m) * GATES + col], U0g[(2 * m + 1) * GATES + col]);
        w1[m] = pk(W1g[(2 * m) * GATES + col], W1g[(2 * m + 1) * GATES + col]);
        u1[m] = pk(U1g[(2 * m) * GATES + col], U1g[(2 * m + 1) * GATES + col]);
    }
    const float bias1 = b1g[col];

    float c0 = 0.f, c1 = 0.f, c2 = 0.f;   // valid on g==0 lanes
    if (j < UNITS) {
        h0buf[0][j] = 0.f; h0buf[1][j] = 0.f;
        h1buf[0][j] = 0.f; h1buf[1][j] = 0.f;
        h2buf[0][j] = 0.f; h2buf[1][j] = 0.f;
    }
    __syncthreads();

    const float* prep = g_pre0 + (size_t)b * SEQ * GATES + j;
    float pre = *prep;                    // pre for tau=0

// One pipeline tick. DC0/DC1/DC2 are compile-time 0/1 literals.
#define UPDATE_CELL(ZA, ZB, CV, DST)                                        \
    {                                                                       \
        float z_ = red4(ZA, ZB);                                            \
        float a_  = gate_act(z_, am2, as);                                  \
        float v1_ = __shfl_xor_sync(0xffffffffu, a_, 1);                    \
        float v2_ = __shfl_xor_sync(0xffffffffu, a_, 2);                    \
        float v3_ = __shfl_xor_sync(0xffffffffu, a_, 3);                    \
        CV = v1_ * CV + a_ * v2_;                                           \
        float h_ = v3_ * tanh_fast(CV);                                     \
        if (wr) (DST)[u] = h_;                                              \
    }

#define TICK(TAU, DC0, DC1, DC2)                                            \
    {                                                                       \
        const int rp_ = (TAU) & 1, wp_ = rp_ ^ 1;                           \
        const float4* H0_ = (const float4*)h0buf[rp_];                      \
        const float4* H1_ = (const float4*)h1buf[rp_];                      \
        const float4* H2_ = (const float4*)h2buf[rp_];                      \
        u64 z0a = pk(pre, 0.f),   z0b = 0ull;                               \
        u64 z1a = pk(bias1, 0.f), z1b = 0ull, z1c = 0ull, z1d = 0ull;       \
        u64 z2a = pk(bias1, 0.f), z2b = 0ull, z2c = 0ull, z2d = 0ull;       \
        prep += GATES;                                                      \
        pre = *prep;                                                        \
        _Pragma("unroll")                                                   \
        for (int m = 0; m < 16; m++) {                                      \
            float4 q0 = H0_[m];                                             \
            u64 a0 = pk(q0.x, q0.y), a1 = pk(q0.z, q0.w);                   \
            if (DC0) { fma2(z0a, a0, u0[2*m]); fma2(z0b, a1, u0[2*m+1]); }  \
            if (DC1) { fma2(z1a, a0, w1[2*m]); fma2(z1b, a1, w1[2*m+1]); }  \
            float4 q1 = H1_[m];                                             \
            u64 b0v = pk(q1.x, q1.y), b1v = pk(q1.z, q1.w);                 \
            if (DC1) { fma2(z1c, b0v, u1[2*m]); fma2(z1d, b1v, u1[2*m+1]); }\
            if (DC2) { fma2(z2a, b0v, w1[2*m]); fma2(z2b, b1v, w1[2*m+1]); }\
            float4 q2 = H2_[m];                                             \
            if (DC2) { fma2(z2c, pk(q2.x, q2.y), u1[2*m]);                  \
                       fma2(z2d, pk(q2.z, q2.w), u1[2*m+1]); }              \
        }                                                                   \
        if (DC0) UPDATE_CELL(z0a, z0b, c0, h0buf[wp_]);                     \
        if (DC1) { z1a = addx2(z1a, z1c); z1b = addx2(z1b, z1d);            \
                   UPDATE_CELL(z1a, z1b, c1, h1buf[wp_]); }                 \
        if (DC2) { z2a = addx2(z2a, z2c); z2b = addx2(z2b, z2d);            \
                   UPDATE_CELL(z2a, z2b, c2, h2buf[wp_]); }                 \
        __syncthreads();                                                    \
    }

    // Warm-up (peeled)
    TICK(0, 1, 0, 0)
    TICK(1, 1, 1, 0)
    // Branch-free main loop: tau = 2 .. SEQ-1  (2046 ticks, even count)
#pragma unroll 2
    for (int tau = 2; tau < SEQ; tau++) {
        TICK(tau, 1, 1, 1)
    }
    // Drain (peeled)
    TICK(SEQ,     0, 1, 1)
    TICK(SEQ + 1, 0, 0, 1)

#undef TICK
#undef UPDATE_CELL

    // Final h2(SEQ-1) written at tick SEQ+1 to parity ((SEQ+1)&1)^1 = SEQ&1.
    const float* h2f = h2buf[SEQ & 1];

    // ---------------- Epilogue: y = relu(h2 @ Wf + bf) @ Wo + bo ------------
    if (j < 64) {
        float acc = bfv[j];
#pragma unroll
        for (int k = 0; k < 64; k++) acc = fmaf(h2f[k], Wf[k * 64 + j], acc);
        fs[j] = fmaxf(acc, 0.f);
    }
    __syncthreads();
    if (j < OUTD) {
        float acc = bo[j];
#pragma unroll
        for (int k = 0; k < 64; k++) acc = fmaf(fs[k], Wo[k * OUTD + j], acc);
        out[b * OUTD + j] = acc;
    }
}

// ===========================================================================
extern "C" void kernel_launch(void* const* d_in, const int* in_sizes, int n_in,
                              void* d_out, int out_size)
{
    const float* x  = (const float*)d_in[0];
    const float* W0 = (const float*)d_in[1];
    const float* U0 = (const float*)d_in[2];
    const float* b0 = (const float*)d_in[3];
    const float* W1 = (const float*)d_in[4];
    const float* U1 = (const float*)d_in[5];
    const float* b1 = (const float*)d_in[6];
    const float* Wf = (const float*)d_in[7];
    const float* bf = (const float*)d_in[8];
    const float* Wo = (const float*)d_in[9];
    const float* bo = (const float*)d_in[10];

    dim3 pg(BATCH, SEQ / 128);
    precompute_kernel<<<pg, 256>>>(x, W0, b0);
    rnn_kernel<<<BATCH, 256>>>(U0, W1, U1, b1, Wf, bf, Wo, bo, (float*)d_out);
}